// round 5
// baseline (speedup 1.0000x reference)
#include <cuda_runtime.h>
#include <math.h>

#define Bq    4
#define Sq    1024
#define Cdim  256
#define INNERq 512
#define NHq   8
#define DHq   64

// ---------------- scratch (static __device__, no allocation) ----------------
__device__ float g_xm[Bq*Sq*INNERq];
__device__ float g_z [Bq*Sq*INNERq];
__device__ float g_xa[Bq*Sq*INNERq];
__device__ float g_q [Bq*Sq*INNERq];
__device__ float g_k [Bq*Sq*INNERq];
__device__ float g_v [Bq*Sq*INNERq];
__device__ float g_ig[Bq*NHq*Sq];
__device__ float g_fg[Bq*NHq*Sq];
__device__ float g_lc[Bq*NHq*Sq];
__device__ float g_h [Bq*Sq*INNERq];

// ---------------- NT GEMM: C[m,n] = sum_k A[m,k]*B[n,k] ----------------
template<int MODE>
__global__ __launch_bounds__(256) void gemm_nt(
    const float* __restrict__ Aext, const float* __restrict__ Bm,
    float* __restrict__ outext, int Kd)
{
    __shared__ float As[16][65];
    __shared__ float Bs[16][65];
    const float* A = (MODE == 0) ? Aext : g_h;
    int tid = threadIdx.x;
    int m0 = blockIdx.y * 64, n0 = blockIdx.x * 64;
    int ty = tid >> 4, tx = tid & 15;
    int lr  = tid >> 2;
    int lc4 = (tid & 3) << 2;
    float acc[4][4] = {};
    const float* Ap = A  + (size_t)(m0 + lr) * Kd + lc4;
    const float* Bp = Bm + (size_t)(n0 + lr) * Kd + lc4;
    for (int k0 = 0; k0 < Kd; k0 += 16) {
        float4 av = *(const float4*)(Ap + k0);
        float4 bv = *(const float4*)(Bp + k0);
        As[lc4+0][lr] = av.x; As[lc4+1][lr] = av.y; As[lc4+2][lr] = av.z; As[lc4+3][lr] = av.w;
        Bs[lc4+0][lr] = bv.x; Bs[lc4+1][lr] = bv.y; Bs[lc4+2][lr] = bv.z; Bs[lc4+3][lr] = bv.w;
        __syncthreads();
        #pragma unroll
        for (int kk = 0; kk < 16; kk++) {
            float a[4], b[4];
            #pragma unroll
            for (int i = 0; i < 4; i++) { a[i] = As[kk][ty*4+i]; b[i] = Bs[kk][tx*4+i]; }
            #pragma unroll
            for (int i = 0; i < 4; i++)
                #pragma unroll
                for (int j = 0; j < 4; j++) acc[i][j] += a[i] * b[j];
        }
        __syncthreads();
    }
    #pragma unroll
    for (int i = 0; i < 4; i++) {
        int m = m0 + ty*4 + i;
        #pragma unroll
        for (int j = 0; j < 4; j++) {
            int n = n0 + tx*4 + j;
            if (MODE == 0) {
                if (n < INNERq) g_xm[(size_t)m * INNERq + n] = acc[i][j];
                else            g_z [(size_t)m * INNERq + (n - INNERq)] = acc[i][j];
            } else {
                outext[(size_t)m * Cdim + n] = acc[i][j];
            }
        }
    }
}

// ---------------- fused conv + silu + per-block qkv + gate dots ----------------
__global__ __launch_bounds__(128) void fused_conv_qkv_gates(
    const float* __restrict__ conv_w, const float* __restrict__ conv_b,
    const float* __restrict__ Wq, const float* __restrict__ Wk, const float* __restrict__ Wv,
    const float* __restrict__ W_i, const float* __restrict__ b_i,
    const float* __restrict__ W_f, const float* __restrict__ b_f)
{
    __shared__ float sh[3 * INNERq];
    int bs = blockIdx.x;
    int b = bs >> 10;
    int s = bs & 1023;
    int t = threadIdx.x;
    size_t rowbase = (size_t)bs * INNERq;

    float xm4[4], xa4[4];
    #pragma unroll
    for (int j = 0; j < 4; j++) {
        int c = t*4 + j;
        float a = conv_b[c];
        #pragma unroll
        for (int kk = 0; kk < 4; kk++) {
            int sp = s - 3 + kk;
            if (sp >= 0) a += g_xm[((size_t)(b*Sq + sp)) * INNERq + c] * conv_w[c*4 + kk];
        }
        float sg = 1.f / (1.f + __expf(-a));
        xa4[j] = a * sg;
        g_xa[rowbase + c] = xa4[j];
        xm4[j] = g_xm[rowbase + c];
    }

    float q4[4], k4[4], v4[4];
    #pragma unroll
    for (int o = 0; o < 4; o++) {
        float aq = 0.f, ak = 0.f, av = 0.f;
        #pragma unroll
        for (int d = 0; d < 4; d++) {
            aq += Wq[t*16 + o*4 + d] * xa4[d];
            ak += Wk[t*16 + o*4 + d] * xa4[d];
            av += Wv[t*16 + o*4 + d] * xm4[d];
        }
        q4[o] = aq; k4[o] = ak; v4[o] = av;
        sh[t*4 + o]            = aq;
        sh[INNERq + t*4 + o]   = ak;
        sh[2*INNERq + t*4 + o] = av;
    }
    *(float4*)&g_q[rowbase + t*4] = make_float4(q4[0], q4[1], q4[2], q4[3]);
    *(float4*)&g_k[rowbase + t*4] = make_float4(k4[0], k4[1], k4[2], k4[3]);
    *(float4*)&g_v[rowbase + t*4] = make_float4(v4[0], v4[1], v4[2], v4[3]);
    __syncthreads();

    int w = t >> 5, l = t & 31;
    #pragma unroll
    for (int g4 = 0; g4 < 4; g4++) {
        int g = w*4 + g4;
        int h = g & 7;
        const float* Wt = (g < 8 ? W_i : W_f) + h * 1536;
        float acc = 0.f;
        for (int idx = l*4; idx < 1536; idx += 128) {
            float4 sv = *(const float4*)&sh[idx];
            float4 wv = *(const float4*)&Wt[idx];
            acc += sv.x*wv.x + sv.y*wv.y + sv.z*wv.z + sv.w*wv.w;
        }
        #pragma unroll
        for (int o = 16; o; o >>= 1) acc += __shfl_xor_sync(0xffffffffu, acc, o);
        if (l == 0) {
            if (g < 8) g_ig[(size_t)(b*NHq + h) * Sq + s] = acc + b_i[h];
            else       g_fg[(size_t)(b*NHq + h) * Sq + s] = acc + b_f[h];
        }
    }
}

// ---------------- log-sigmoid + inclusive cumsum over S per (b,h) ----------------
__global__ __launch_bounds__(1024) void scan_kernel()
{
    int bh = blockIdx.x;
    int s = threadIdx.x;
    float x = g_fg[(size_t)bh * Sq + s];
    float lf = fminf(x, 0.f) - log1pf(expf(-fabsf(x)));
    __shared__ float sc[Sq];
    sc[s] = lf;
    __syncthreads();
    for (int off = 1; off < Sq; off <<= 1) {
        float tv = (s >= off) ? sc[s - off] : 0.f;
        __syncthreads();
        sc[s] += tv;
        __syncthreads();
    }
    g_lc[(size_t)bh * Sq + s] = sc[s];
}

// ---------------- streaming mLSTM attention v2c ----------------
// 256 threads: thread = (row r = t>>2, quarter qd = t&3).
// wgt factored: wgt = Ei * ej[jj]; ej once per tile (warp 0).
// DEADLOCK FIX: inner loop trip count is warp-uniform (jmaxW); per-lane
// causal mask applied to p AFTER the shuffle, so shuffles never diverge.
__global__ __launch_bounds__(256) void attn_kernel(
    const float* __restrict__ norm_w, const float* __restrict__ skipw)
{
    int xblk = blockIdx.x;             // 0..511
    int it = 15 - (xblk >> 5);         // biggest tiles first
    int bh = xblk & 31;
    int b = bh >> 3, h = bh & 7;
    int i0 = it * 64;
    int t = threadIdx.x;
    int r = t >> 2;
    int qd = t & 3;
    int i = i0 + r;

    __shared__ float ks[64][64];
    __shared__ float vs[64][64];
    __shared__ float pm[64];
    __shared__ float ej[64];
    __shared__ float s_pmAll;

    float qr[16];
    size_t qbase = ((size_t)(b*Sq + i)) * INNERq + h*DHq + qd*16;
    #pragma unroll
    for (int d4 = 0; d4 < 4; d4++) {
        float4 v = *(const float4*)&g_q[qbase + d4*4];
        qr[d4*4+0] = v.x; qr[d4*4+1] = v.y; qr[d4*4+2] = v.z; qr[d4*4+3] = v.w;
    }
    float lci = g_lc[(size_t)bh * Sq + i];

    float acc[16];
    #pragma unroll
    for (int d = 0; d < 16; d++) acc[d] = 0.f;
    float m = -3.4e38f, ssum = 0.f;

    int jmaxW_diag = (((t | 31) >> 2) + 1);   // warp-uniform: max row in warp + 1

    for (int jt = 0; jt <= it; jt++) {
        int j0 = jt * 64;
        #pragma unroll
        for (int e4 = 0; e4 < 4; e4++) {
            int e   = t + 256 * e4;
            int row = e >> 4;
            int c4  = (e & 15) << 2;
            size_t gb = ((size_t)(b*Sq + j0 + row)) * INNERq + h*DHq + c4;
            float4 kv = *(const float4*)&g_k[gb];
            kv.x *= 0.125f; kv.y *= 0.125f; kv.z *= 0.125f; kv.w *= 0.125f;
            *(float4*)&ks[row][c4] = kv;
            *(float4*)&vs[row][c4] = *(const float4*)&g_v[gb];
        }
        if (t < 32) {
            int l = t;
            size_t gbase = (size_t)bh * Sq + j0;
            float a0 = g_ig[gbase + l]      - g_lc[gbase + l];
            float a1 = g_ig[gbase + 32 + l] - g_lc[gbase + 32 + l];
            float p0 = a0;
            #pragma unroll
            for (int off = 1; off < 32; off <<= 1) {
                float u = __shfl_up_sync(0xffffffffu, p0, off);
                if (l >= off) p0 = fmaxf(p0, u);
            }
            float max0 = __shfl_sync(0xffffffffu, p0, 31);
            float p1 = a1;
            #pragma unroll
            for (int off = 1; off < 32; off <<= 1) {
                float u = __shfl_up_sync(0xffffffffu, p1, off);
                if (l >= off) p1 = fmaxf(p1, u);
            }
            p1 = fmaxf(p1, max0);
            float pmAll = __shfl_sync(0xffffffffu, p1, 31);
            pm[l]      = p0;
            pm[32 + l] = p1;
            ej[l]      = __expf(a0 - pmAll);
            ej[32 + l] = __expf(a1 - pmAll);
            if (l == 0) s_pmAll = pmAll;
        }
        __syncthreads();

        bool diag = (jt == it);
        int jmax  = diag ? (r + 1) : 64;        // per-lane causal bound
        int jloop = diag ? jmaxW_diag : 64;     // warp-uniform trip count
        float pmAll  = s_pmAll;
        float rowmax = lci + pm[jmax - 1];
        float mnew = fmaxf(m, rowmax);
        float sc = __expf(m - mnew);            // ==1 if unchanged; ==0 first tile
        m = mnew;
        ssum *= sc;
        #pragma unroll
        for (int d = 0; d < 16; d++) acc[d] *= sc;
        float Ei = __expf(lci + pmAll - m);

        const float* ksr = &ks[0][qd*16];
        const float* vsr = &vs[0][qd*16];
        for (int jj = 0; jj < jloop; jj++) {
            float4 k0 = *(const float4*)(ksr + jj*64 + 0);
            float4 k1 = *(const float4*)(ksr + jj*64 + 4);
            float4 k2 = *(const float4*)(ksr + jj*64 + 8);
            float4 k3 = *(const float4*)(ksr + jj*64 + 12);
            float s0 = qr[0]*k0.x + qr[4]*k1.x + qr[8] *k2.x + qr[12]*k3.x;
            float s1 = qr[1]*k0.y + qr[5]*k1.y + qr[9] *k2.y + qr[13]*k3.y;
            float s2 = qr[2]*k0.z + qr[6]*k1.z + qr[10]*k2.z + qr[14]*k3.z;
            float s3 = qr[3]*k0.w + qr[7]*k1.w + qr[11]*k2.w + qr[15]*k3.w;
            float sdot = (s0 + s1) + (s2 + s3);
            sdot += __shfl_xor_sync(0xffffffffu, sdot, 1);   // whole warp participates
            sdot += __shfl_xor_sync(0xffffffffu, sdot, 2);
            float p = sdot * Ei * ej[jj];
            if (jj >= jmax) p = 0.f;                         // causal mask after shuffle
            ssum += p;
            float4 v0 = *(const float4*)(vsr + jj*64 + 0);
            float4 v1 = *(const float4*)(vsr + jj*64 + 4);
            float4 v2 = *(const float4*)(vsr + jj*64 + 8);
            float4 v3 = *(const float4*)(vsr + jj*64 + 12);
            acc[0] += p*v0.x; acc[1] += p*v0.y; acc[2]  += p*v0.z; acc[3]  += p*v0.w;
            acc[4] += p*v1.x; acc[5] += p*v1.y; acc[6]  += p*v1.z; acc[7]  += p*v1.w;
            acc[8] += p*v2.x; acc[9] += p*v2.y; acc[10] += p*v2.z; acc[11] += p*v2.w;
            acc[12]+= p*v3.x; acc[13]+= p*v3.y; acc[14] += p*v3.z; acc[15] += p*v3.w;
        }
        __syncthreads();
    }

    // epilogue
    float denom = fmaxf(fabsf(ssum), __expf(-m)) + 1e-6f;
    float inv = 1.f / denom;
    float mean = 0.f;
    #pragma unroll
    for (int d = 0; d < 16; d++) { acc[d] *= inv; mean += acc[d]; }
    mean += __shfl_xor_sync(0xffffffffu, mean, 1);
    mean += __shfl_xor_sync(0xffffffffu, mean, 2);
    mean *= (1.f / 64.f);
    float var = 0.f;
    #pragma unroll
    for (int d = 0; d < 16; d++) { float df = acc[d] - mean; var += df * df; }
    var += __shfl_xor_sync(0xffffffffu, var, 1);
    var += __shfl_xor_sync(0xffffffffu, var, 2);
    var *= (1.f / 64.f);
    float rstd = rsqrtf(var + 1e-5f);
    size_t obase = ((size_t)(b*Sq + i)) * INNERq + h*DHq + qd*16;
    #pragma unroll
    for (int d = 0; d < 16; d++) {
        int c = h*DHq + qd*16 + d;
        float hn  = (acc[d] - mean) * rstd * norm_w[c];
        float za  = g_z[obase + d];
        float sil = za / (1.f + __expf(-za));
        g_h[obase + d] = (hn + skipw[c] * g_xa[obase + d]) * sil;
    }
}

// ---------------- launch (kernel launches ONLY — graph-capturable) ----------------
extern "C" void kernel_launch(void* const* d_in, const int* in_sizes, int n_in,
                              void* d_out, int out_size)
{
    const float* x      = (const float*)d_in[0];
    const float* W_up   = (const float*)d_in[1];
    const float* conv_w = (const float*)d_in[2];
    const float* conv_b = (const float*)d_in[3];
    const float* Wq     = (const float*)d_in[4];
    const float* Wk     = (const float*)d_in[5];
    const float* Wv     = (const float*)d_in[6];
    const float* W_i    = (const float*)d_in[7];
    const float* b_i    = (const float*)d_in[8];
    const float* W_f    = (const float*)d_in[9];
    const float* b_f    = (const float*)d_in[10];
    const float* norm_w = (const float*)d_in[11];
    const float* skipw  = (const float*)d_in[12];
    const float* W_down = (const float*)d_in[13];
    float* out = (float*)d_out;

    gemm_nt<0><<<dim3(16, 64), 256>>>(x, W_up, nullptr, Cdim);
    fused_conv_qkv_gates<<<Bq*Sq, 128>>>(conv_w, conv_b, Wq, Wk, Wv, W_i, b_i, W_f, b_f);
    scan_kernel<<<Bq*NHq, 1024>>>();
    attn_kernel<<<512, 256>>>(norm_w, skipw);
    gemm_nt<1><<<dim3(4, 64), 256>>>(nullptr, W_down, out, INNERq);
}

// round 6
// speedup vs baseline: 1.8984x; 1.8984x over previous
#include <cuda_runtime.h>
#include <math.h>

#define Bq    4
#define Sq    1024
#define Cdim  256
#define INNERq 512
#define NHq   8
#define DHq   64

// ---------------- scratch (static __device__, no allocation) ----------------
__device__ float g_xm[Bq*Sq*INNERq];
__device__ float g_z [Bq*Sq*INNERq];
__device__ float g_xa[Bq*Sq*INNERq];
__device__ float g_q [Bq*Sq*INNERq];
__device__ float g_k [Bq*Sq*INNERq];
__device__ float g_v [Bq*Sq*INNERq];
__device__ float g_ig[Bq*NHq*Sq];
__device__ float g_fg[Bq*NHq*Sq];
__device__ float g_lc[Bq*NHq*Sq];
__device__ float g_h [Bq*Sq*INNERq];

// ---------------- NT GEMM: C[m,n] = sum_k A[m,k]*B[n,k] ----------------
template<int MODE>
__global__ __launch_bounds__(256) void gemm_nt(
    const float* __restrict__ Aext, const float* __restrict__ Bm,
    float* __restrict__ outext, int Kd)
{
    __shared__ float As[16][65];
    __shared__ float Bs[16][65];
    const float* A = (MODE == 0) ? Aext : g_h;
    int tid = threadIdx.x;
    int m0 = blockIdx.y * 64, n0 = blockIdx.x * 64;
    int ty = tid >> 4, tx = tid & 15;
    int lr  = tid >> 2;
    int lc4 = (tid & 3) << 2;
    float acc[4][4] = {};
    const float* Ap = A  + (size_t)(m0 + lr) * Kd + lc4;
    const float* Bp = Bm + (size_t)(n0 + lr) * Kd + lc4;
    for (int k0 = 0; k0 < Kd; k0 += 16) {
        float4 av = *(const float4*)(Ap + k0);
        float4 bv = *(const float4*)(Bp + k0);
        As[lc4+0][lr] = av.x; As[lc4+1][lr] = av.y; As[lc4+2][lr] = av.z; As[lc4+3][lr] = av.w;
        Bs[lc4+0][lr] = bv.x; Bs[lc4+1][lr] = bv.y; Bs[lc4+2][lr] = bv.z; Bs[lc4+3][lr] = bv.w;
        __syncthreads();
        #pragma unroll
        for (int kk = 0; kk < 16; kk++) {
            float a[4], b[4];
            #pragma unroll
            for (int i = 0; i < 4; i++) { a[i] = As[kk][ty*4+i]; b[i] = Bs[kk][tx*4+i]; }
            #pragma unroll
            for (int i = 0; i < 4; i++)
                #pragma unroll
                for (int j = 0; j < 4; j++) acc[i][j] += a[i] * b[j];
        }
        __syncthreads();
    }
    #pragma unroll
    for (int i = 0; i < 4; i++) {
        int m = m0 + ty*4 + i;
        #pragma unroll
        for (int j = 0; j < 4; j++) {
            int n = n0 + tx*4 + j;
            if (MODE == 0) {
                if (n < INNERq) g_xm[(size_t)m * INNERq + n] = acc[i][j];
                else            g_z [(size_t)m * INNERq + (n - INNERq)] = acc[i][j];
            } else {
                outext[(size_t)m * Cdim + n] = acc[i][j];
            }
        }
    }
}

// ---------------- fused conv + silu + per-block qkv + gate dots ----------------
__global__ __launch_bounds__(128) void fused_conv_qkv_gates(
    const float* __restrict__ conv_w, const float* __restrict__ conv_b,
    const float* __restrict__ Wq, const float* __restrict__ Wk, const float* __restrict__ Wv,
    const float* __restrict__ W_i, const float* __restrict__ b_i,
    const float* __restrict__ W_f, const float* __restrict__ b_f)
{
    __shared__ float sh[3 * INNERq];
    int bs = blockIdx.x;
    int b = bs >> 10;
    int s = bs & 1023;
    int t = threadIdx.x;
    size_t rowbase = (size_t)bs * INNERq;

    float xm4[4], xa4[4];
    #pragma unroll
    for (int j = 0; j < 4; j++) {
        int c = t*4 + j;
        float a = conv_b[c];
        #pragma unroll
        for (int kk = 0; kk < 4; kk++) {
            int sp = s - 3 + kk;
            if (sp >= 0) a += g_xm[((size_t)(b*Sq + sp)) * INNERq + c] * conv_w[c*4 + kk];
        }
        float sg = 1.f / (1.f + __expf(-a));
        xa4[j] = a * sg;
        g_xa[rowbase + c] = xa4[j];
        xm4[j] = g_xm[rowbase + c];
    }

    float q4[4], k4[4], v4[4];
    #pragma unroll
    for (int o = 0; o < 4; o++) {
        float aq = 0.f, ak = 0.f, av = 0.f;
        #pragma unroll
        for (int d = 0; d < 4; d++) {
            aq += Wq[t*16 + o*4 + d] * xa4[d];
            ak += Wk[t*16 + o*4 + d] * xa4[d];
            av += Wv[t*16 + o*4 + d] * xm4[d];
        }
        q4[o] = aq; k4[o] = ak; v4[o] = av;
        sh[t*4 + o]            = aq;
        sh[INNERq + t*4 + o]   = ak;
        sh[2*INNERq + t*4 + o] = av;
    }
    *(float4*)&g_q[rowbase + t*4] = make_float4(q4[0], q4[1], q4[2], q4[3]);
    *(float4*)&g_k[rowbase + t*4] = make_float4(k4[0], k4[1], k4[2], k4[3]);
    *(float4*)&g_v[rowbase + t*4] = make_float4(v4[0], v4[1], v4[2], v4[3]);
    __syncthreads();

    int w = t >> 5, l = t & 31;
    #pragma unroll
    for (int g4 = 0; g4 < 4; g4++) {
        int g = w*4 + g4;
        int h = g & 7;
        const float* Wt = (g < 8 ? W_i : W_f) + h * 1536;
        float acc = 0.f;
        for (int idx = l*4; idx < 1536; idx += 128) {
            float4 sv = *(const float4*)&sh[idx];
            float4 wv = *(const float4*)&Wt[idx];
            acc += sv.x*wv.x + sv.y*wv.y + sv.z*wv.z + sv.w*wv.w;
        }
        #pragma unroll
        for (int o = 16; o; o >>= 1) acc += __shfl_xor_sync(0xffffffffu, acc, o);
        if (l == 0) {
            if (g < 8) g_ig[(size_t)(b*NHq + h) * Sq + s] = acc + b_i[h];
            else       g_fg[(size_t)(b*NHq + h) * Sq + s] = acc + b_f[h];
        }
    }
}

// ---------------- log-sigmoid + inclusive cumsum over S per (b,h) ----------------
__global__ __launch_bounds__(1024) void scan_kernel()
{
    int bh = blockIdx.x;
    int s = threadIdx.x;
    float x = g_fg[(size_t)bh * Sq + s];
    float lf = fminf(x, 0.f) - log1pf(expf(-fabsf(x)));
    __shared__ float sc[Sq];
    sc[s] = lf;
    __syncthreads();
    for (int off = 1; off < Sq; off <<= 1) {
        float tv = (s >= off) ? sc[s - off] : 0.f;
        __syncthreads();
        sc[s] += tv;
        __syncthreads();
    }
    g_lc[(size_t)bh * Sq + s] = sc[s];
}

// ---------------- streaming mLSTM attention v3: two register-tiled GEMMs ----------------
// Block: 64 q-rows, j-tiles of 32. 256 threads: ty=t>>4 (row group of 4), tx=t&15.
// Phase 1: S = Q@K^T (4x2 per thread), weights p = s*Ei[row]*ej[col], store P^T,
//          row-sums via tx-butterfly. Phase 2: O += P@V (4x4 per thread).
__global__ __launch_bounds__(256) void attn_kernel(
    const float* __restrict__ norm_w, const float* __restrict__ skipw)
{
    int xblk = blockIdx.x;             // 0..511
    int it = 15 - (xblk >> 5);         // biggest tiles first
    int bh = xblk & 31;
    int b = bh >> 3, h = bh & 7;
    int i0 = it * 64;
    int t = threadIdx.x;
    int tx = t & 15, ty = t >> 4;

    __shared__ float Qt[64][68];   // Q transposed [dim][row] (reused as O at end)
    __shared__ float Kt[64][36];   // K transposed [dim][j], scaled by 1/8
    __shared__ float Vs[32][68];   // V row-major [j][dim]
    __shared__ float Pt[32][68];   // P transposed [j][row]
    __shared__ float pm[32], ej[32];
    __shared__ float m_row[64], sc_row[64], Ei_row[64], ssum_row[64], lci_row[64];
    __shared__ float s_pmAll;

    // load Q tile transposed (once per block)
    #pragma unroll
    for (int e4 = 0; e4 < 4; e4++) {
        int e = t + 256 * e4;
        int row = e >> 4, c4 = (e & 15) << 2;
        float4 qv = *(const float4*)&g_q[((size_t)(b*Sq + i0 + row)) * INNERq + h*DHq + c4];
        Qt[c4+0][row] = qv.x; Qt[c4+1][row] = qv.y; Qt[c4+2][row] = qv.z; Qt[c4+3][row] = qv.w;
    }
    if (t < 64) {
        lci_row[t]  = g_lc[(size_t)bh*Sq + i0 + t];
        m_row[t]    = -3.4e38f;
        ssum_row[t] = 0.f;
    }

    float acc[4][4];
    #pragma unroll
    for (int a = 0; a < 4; a++)
        #pragma unroll
        for (int d = 0; d < 4; d++) acc[a][d] = 0.f;

    int ntiles = 2*it + 2;
    for (int jt = 0; jt < ntiles; jt++) {
        int j0 = jt * 32;
        __syncthreads();   // previous tile fully consumed
        // load K (transposed, scaled) and V
        #pragma unroll
        for (int e4 = 0; e4 < 2; e4++) {
            int e = t + 256*e4;
            int row = e >> 4, c4 = (e & 15) << 2;
            size_t gb = ((size_t)(b*Sq + j0 + row)) * INNERq + h*DHq + c4;
            float4 kv = *(const float4*)&g_k[gb];
            Kt[c4+0][row] = kv.x*0.125f; Kt[c4+1][row] = kv.y*0.125f;
            Kt[c4+2][row] = kv.z*0.125f; Kt[c4+3][row] = kv.w*0.125f;
            *(float4*)&Vs[row][c4] = *(const float4*)&g_v[gb];
        }
        // warp 0: gl = ig - lc, prefix max, ej
        if (t < 32) {
            size_t gbase = (size_t)bh*Sq + j0;
            float a0 = g_ig[gbase + t] - g_lc[gbase + t];
            float p0 = a0;
            #pragma unroll
            for (int off = 1; off < 32; off <<= 1) {
                float u = __shfl_up_sync(0xffffffffu, p0, off);
                if (t >= off) p0 = fmaxf(p0, u);
            }
            float pmAll = __shfl_sync(0xffffffffu, p0, 31);
            pm[t] = p0;
            ej[t] = __expf(a0 - pmAll);
            if (t == 0) s_pmAll = pmAll;
        }
        __syncthreads();
        // per-row state update
        if (t < 64) {
            int r = t;
            int jm = i0 + r - j0 + 1;
            jm = jm > 32 ? 32 : jm;
            float mo = m_row[r];
            if (jm > 0) {
                float rowmax = lci_row[r] + pm[jm-1];
                float mnew = fmaxf(mo, rowmax);
                float sc = __expf(mo - mnew);     // 0 on first tile, 1 if unchanged
                sc_row[r] = sc;
                Ei_row[r] = __expf(lci_row[r] + s_pmAll - mnew);
                m_row[r]  = mnew;
                ssum_row[r] *= sc;
            } else {
                sc_row[r] = 1.f;
                Ei_row[r] = 0.f;
            }
        }
        __syncthreads();
        // rescale O accumulators
        #pragma unroll
        for (int a = 0; a < 4; a++) {
            float sc = sc_row[4*ty + a];
            #pragma unroll
            for (int d = 0; d < 4; d++) acc[a][d] *= sc;
        }
        // phase 1: S(4x2) = Q @ K^T
        float s[4][2] = {};
        #pragma unroll 8
        for (int kk = 0; kk < 64; kk++) {
            float4 aq = *(const float4*)&Qt[kk][4*ty];
            float2 bk = *(const float2*)&Kt[kk][2*tx];
            s[0][0] += aq.x*bk.x; s[0][1] += aq.x*bk.y;
            s[1][0] += aq.y*bk.x; s[1][1] += aq.y*bk.y;
            s[2][0] += aq.z*bk.x; s[2][1] += aq.z*bk.y;
            s[3][0] += aq.w*bk.x; s[3][1] += aq.w*bk.y;
        }
        // weights + causal mask + P^T store + row-sum butterfly
        {
            float ej0 = ej[2*tx], ej1 = ej[2*tx+1];
            int jg0 = j0 + 2*tx;
            #pragma unroll
            for (int a = 0; a < 4; a++) {
                int ig = i0 + 4*ty + a;
                float Ei = Ei_row[4*ty + a];
                float p0 = (jg0     <= ig) ? s[a][0]*Ei*ej0 : 0.f;
                float p1 = (jg0 + 1 <= ig) ? s[a][1]*Ei*ej1 : 0.f;
                Pt[2*tx+0][4*ty+a] = p0;
                Pt[2*tx+1][4*ty+a] = p1;
                float part = p0 + p1;
                part += __shfl_xor_sync(0xffffffffu, part, 1);
                part += __shfl_xor_sync(0xffffffffu, part, 2);
                part += __shfl_xor_sync(0xffffffffu, part, 4);
                part += __shfl_xor_sync(0xffffffffu, part, 8);
                if (tx == 0) ssum_row[4*ty + a] += part;
            }
        }
        __syncthreads();
        // phase 2: O(4x4) += P @ V
        #pragma unroll 4
        for (int jj = 0; jj < 32; jj++) {
            float4 pa = *(const float4*)&Pt[jj][4*ty];
            float4 vb = *(const float4*)&Vs[jj][4*tx];
            acc[0][0] += pa.x*vb.x; acc[0][1] += pa.x*vb.y; acc[0][2] += pa.x*vb.z; acc[0][3] += pa.x*vb.w;
            acc[1][0] += pa.y*vb.x; acc[1][1] += pa.y*vb.y; acc[1][2] += pa.y*vb.z; acc[1][3] += pa.y*vb.w;
            acc[2][0] += pa.z*vb.x; acc[2][1] += pa.z*vb.y; acc[2][2] += pa.z*vb.z; acc[2][3] += pa.z*vb.w;
            acc[3][0] += pa.w*vb.x; acc[3][1] += pa.w*vb.y; acc[3][2] += pa.w*vb.z; acc[3][3] += pa.w*vb.w;
        }
    }

    __syncthreads();
    // stage O into Qt buffer (row-major) for the LN epilogue
    #pragma unroll
    for (int a = 0; a < 4; a++)
        #pragma unroll
        for (int d = 0; d < 4; d++)
            Qt[4*ty + a][4*tx + d] = acc[a][d];
    __syncthreads();

    // LN + skip + silu(z) gate: thread = (row = t>>2, quarter qd = t&3)
    {
        int row = t >> 2, qd = t & 3;
        int i = i0 + row;
        float m    = m_row[row];
        float ssum = ssum_row[row];
        float denom = fmaxf(fabsf(ssum), __expf(-m)) + 1e-6f;
        float inv = 1.f / denom;
        float o[16];
        #pragma unroll
        for (int k4 = 0; k4 < 4; k4++) {
            float4 v = *(const float4*)&Qt[row][qd*16 + k4*4];
            o[k4*4+0] = v.x*inv; o[k4*4+1] = v.y*inv; o[k4*4+2] = v.z*inv; o[k4*4+3] = v.w*inv;
        }
        float mean = 0.f;
        #pragma unroll
        for (int d = 0; d < 16; d++) mean += o[d];
        mean += __shfl_xor_sync(0xffffffffu, mean, 1);
        mean += __shfl_xor_sync(0xffffffffu, mean, 2);
        mean *= (1.f / 64.f);
        float var = 0.f;
        #pragma unroll
        for (int d = 0; d < 16; d++) { float df = o[d] - mean; var += df * df; }
        var += __shfl_xor_sync(0xffffffffu, var, 1);
        var += __shfl_xor_sync(0xffffffffu, var, 2);
        var *= (1.f / 64.f);
        float rstd = rsqrtf(var + 1e-5f);
        size_t obase = ((size_t)(b*Sq + i)) * INNERq + h*DHq + qd*16;
        #pragma unroll
        for (int d = 0; d < 16; d++) {
            int c = h*DHq + qd*16 + d;
            float hn  = (o[d] - mean) * rstd * norm_w[c];
            float za  = g_z[obase + d];
            float sil = za / (1.f + __expf(-za));
            g_h[obase + d] = (hn + skipw[c] * g_xa[obase + d]) * sil;
        }
    }
}

// ---------------- launch (kernel launches ONLY — graph-capturable) ----------------
extern "C" void kernel_launch(void* const* d_in, const int* in_sizes, int n_in,
                              void* d_out, int out_size)
{
    const float* x      = (const float*)d_in[0];
    const float* W_up   = (const float*)d_in[1];
    const float* conv_w = (const float*)d_in[2];
    const float* conv_b = (const float*)d_in[3];
    const float* Wq     = (const float*)d_in[4];
    const float* Wk     = (const float*)d_in[5];
    const float* Wv     = (const float*)d_in[6];
    const float* W_i    = (const float*)d_in[7];
    const float* b_i    = (const float*)d_in[8];
    const float* W_f    = (const float*)d_in[9];
    const float* b_f    = (const float*)d_in[10];
    const float* norm_w = (const float*)d_in[11];
    const float* skipw  = (const float*)d_in[12];
    const float* W_down = (const float*)d_in[13];
    float* out = (float*)d_out;

    gemm_nt<0><<<dim3(16, 64), 256>>>(x, W_up, nullptr, Cdim);
    fused_conv_qkv_gates<<<Bq*Sq, 128>>>(conv_w, conv_b, Wq, Wk, Wv, W_i, b_i, W_f, b_f);
    scan_kernel<<<Bq*NHq, 1024>>>();
    attn_kernel<<<512, 256>>>(norm_w, skipw);
    gemm_nt<1><<<dim3(4, 64), 256>>>(nullptr, W_down, out, INNERq);
}

// round 7
// speedup vs baseline: 2.1131x; 1.1131x over previous
#include <cuda_runtime.h>
#include <math.h>

#define Bq    4
#define Sq    1024
#define Cdim  256
#define INNERq 512
#define NHq   8
#define DHq   64

// ---------------- scratch (static __device__, no allocation) ----------------
__device__ float g_xm[Bq*Sq*INNERq];
__device__ float g_z [Bq*Sq*INNERq];
__device__ float g_xa[Bq*Sq*INNERq];
__device__ float g_q [Bq*Sq*INNERq];
__device__ float g_k [Bq*Sq*INNERq];
__device__ float g_v [Bq*Sq*INNERq];
__device__ float g_ig[Bq*NHq*Sq];
__device__ float g_fg[Bq*NHq*Sq];
__device__ float g_lc[Bq*NHq*Sq];
__device__ float g_h [Bq*Sq*INNERq];

// ---------------- NT GEMM: C[m,n] = sum_k A[m,k]*B[n,k] ----------------
template<int MODE>
__global__ __launch_bounds__(256) void gemm_nt(
    const float* __restrict__ Aext, const float* __restrict__ Bm,
    float* __restrict__ outext, int Kd)
{
    __shared__ float As[16][65];
    __shared__ float Bs[16][65];
    const float* A = (MODE == 0) ? Aext : g_h;
    int tid = threadIdx.x;
    int m0 = blockIdx.y * 64, n0 = blockIdx.x * 64;
    int ty = tid >> 4, tx = tid & 15;
    int lr  = tid >> 2;
    int lc4 = (tid & 3) << 2;
    float acc[4][4] = {};
    const float* Ap = A  + (size_t)(m0 + lr) * Kd + lc4;
    const float* Bp = Bm + (size_t)(n0 + lr) * Kd + lc4;
    for (int k0 = 0; k0 < Kd; k0 += 16) {
        float4 av = *(const float4*)(Ap + k0);
        float4 bv = *(const float4*)(Bp + k0);
        As[lc4+0][lr] = av.x; As[lc4+1][lr] = av.y; As[lc4+2][lr] = av.z; As[lc4+3][lr] = av.w;
        Bs[lc4+0][lr] = bv.x; Bs[lc4+1][lr] = bv.y; Bs[lc4+2][lr] = bv.z; Bs[lc4+3][lr] = bv.w;
        __syncthreads();
        #pragma unroll
        for (int kk = 0; kk < 16; kk++) {
            float a[4], b[4];
            #pragma unroll
            for (int i = 0; i < 4; i++) { a[i] = As[kk][ty*4+i]; b[i] = Bs[kk][tx*4+i]; }
            #pragma unroll
            for (int i = 0; i < 4; i++)
                #pragma unroll
                for (int j = 0; j < 4; j++) acc[i][j] += a[i] * b[j];
        }
        __syncthreads();
    }
    #pragma unroll
    for (int i = 0; i < 4; i++) {
        int m = m0 + ty*4 + i;
        #pragma unroll
        for (int j = 0; j < 4; j++) {
            int n = n0 + tx*4 + j;
            if (MODE == 0) {
                if (n < INNERq) g_xm[(size_t)m * INNERq + n] = acc[i][j];
                else            g_z [(size_t)m * INNERq + (n - INNERq)] = acc[i][j];
            } else {
                outext[(size_t)m * Cdim + n] = acc[i][j];
            }
        }
    }
}

// ---------------- fused conv + silu + per-block qkv + gate dots ----------------
__global__ __launch_bounds__(128) void fused_conv_qkv_gates(
    const float* __restrict__ conv_w, const float* __restrict__ conv_b,
    const float* __restrict__ Wq, const float* __restrict__ Wk, const float* __restrict__ Wv,
    const float* __restrict__ W_i, const float* __restrict__ b_i,
    const float* __restrict__ W_f, const float* __restrict__ b_f)
{
    __shared__ float sh[3 * INNERq];
    int bs = blockIdx.x;
    int b = bs >> 10;
    int s = bs & 1023;
    int t = threadIdx.x;
    size_t rowbase = (size_t)bs * INNERq;

    float xm4[4], xa4[4];
    #pragma unroll
    for (int j = 0; j < 4; j++) {
        int c = t*4 + j;
        float a = conv_b[c];
        #pragma unroll
        for (int kk = 0; kk < 4; kk++) {
            int sp = s - 3 + kk;
            if (sp >= 0) a += g_xm[((size_t)(b*Sq + sp)) * INNERq + c] * conv_w[c*4 + kk];
        }
        float sg = 1.f / (1.f + __expf(-a));
        xa4[j] = a * sg;
        g_xa[rowbase + c] = xa4[j];
        xm4[j] = g_xm[rowbase + c];
    }

    float q4[4], k4[4], v4[4];
    #pragma unroll
    for (int o = 0; o < 4; o++) {
        float aq = 0.f, ak = 0.f, av = 0.f;
        #pragma unroll
        for (int d = 0; d < 4; d++) {
            aq += Wq[t*16 + o*4 + d] * xa4[d];
            ak += Wk[t*16 + o*4 + d] * xa4[d];
            av += Wv[t*16 + o*4 + d] * xm4[d];
        }
        q4[o] = aq; k4[o] = ak; v4[o] = av;
        sh[t*4 + o]            = aq;
        sh[INNERq + t*4 + o]   = ak;
        sh[2*INNERq + t*4 + o] = av;
    }
    *(float4*)&g_q[rowbase + t*4] = make_float4(q4[0], q4[1], q4[2], q4[3]);
    *(float4*)&g_k[rowbase + t*4] = make_float4(k4[0], k4[1], k4[2], k4[3]);
    *(float4*)&g_v[rowbase + t*4] = make_float4(v4[0], v4[1], v4[2], v4[3]);
    __syncthreads();

    int w = t >> 5, l = t & 31;
    #pragma unroll
    for (int g4 = 0; g4 < 4; g4++) {
        int g = w*4 + g4;
        int h = g & 7;
        const float* Wt = (g < 8 ? W_i : W_f) + h * 1536;
        float acc = 0.f;
        for (int idx = l*4; idx < 1536; idx += 128) {
            float4 sv = *(const float4*)&sh[idx];
            float4 wv = *(const float4*)&Wt[idx];
            acc += sv.x*wv.x + sv.y*wv.y + sv.z*wv.z + sv.w*wv.w;
        }
        #pragma unroll
        for (int o = 16; o; o >>= 1) acc += __shfl_xor_sync(0xffffffffu, acc, o);
        if (l == 0) {
            if (g < 8) g_ig[(size_t)(b*NHq + h) * Sq + s] = acc + b_i[h];
            else       g_fg[(size_t)(b*NHq + h) * Sq + s] = acc + b_f[h];
        }
    }
}

// ---------------- log-sigmoid + inclusive cumsum over S per (b,h) ----------------
__global__ __launch_bounds__(1024) void scan_kernel()
{
    int bh = blockIdx.x;
    int s = threadIdx.x;
    float x = g_fg[(size_t)bh * Sq + s];
    float lf = fminf(x, 0.f) - log1pf(expf(-fabsf(x)));
    __shared__ float sc[Sq];
    sc[s] = lf;
    __syncthreads();
    for (int off = 1; off < Sq; off <<= 1) {
        float tv = (s >= off) ? sc[s - off] : 0.f;
        __syncthreads();
        sc[s] += tv;
        __syncthreads();
    }
    g_lc[(size_t)bh * Sq + s] = sc[s];
}

// ---------------- streaming mLSTM attention v4: 64x64 tiles, 4x4 micro ----------------
// Dynamic smem layout (floats):
//   Qt [64][68]  Q^T [dim][row]           (reused as O row-major at epilogue)
//   KV [64][68]  K^T [dim][j] in phase 1, V [j][dim] in phase 2 (same buffer)
//   Pt [64][68]  P row-major [row][j]
//   aux: pm,ej,m_row,sc_row,Ei_row,ssum_row,lci_row (64 each)
#define ATT_STRIDE 68
#define ATT_SMEM_FLOATS (3*64*ATT_STRIDE + 7*64)
#define ATT_SMEM_BYTES  (ATT_SMEM_FLOATS*4)

__global__ __launch_bounds__(256) void attn_kernel(
    const float* __restrict__ norm_w, const float* __restrict__ skipw)
{
    extern __shared__ float sm[];
    float* Qt = sm;                       // [64][68]
    float* KV = Qt + 64*ATT_STRIDE;       // [64][68]
    float* Pt = KV + 64*ATT_STRIDE;       // [64][68]
    float* pm       = Pt + 64*ATT_STRIDE;
    float* ej       = pm + 64;
    float* m_row    = ej + 64;
    float* sc_row   = m_row + 64;
    float* Ei_row   = sc_row + 64;
    float* ssum_row = Ei_row + 64;
    float* lci_row  = ssum_row + 64;

    int xblk = blockIdx.x;             // 0..511
    int it = 15 - (xblk >> 5);         // biggest tiles first
    int bh = xblk & 31;
    int b = bh >> 3, h = bh & 7;
    int i0 = it * 64;
    int t = threadIdx.x;
    int tx = t & 15, ty = t >> 4;

    // load Q^T, init per-row state
    #pragma unroll
    for (int e4 = 0; e4 < 4; e4++) {
        int e = t + 256 * e4;
        int row = e >> 4, c4 = (e & 15) << 2;
        float4 qv = *(const float4*)&g_q[((size_t)(b*Sq + i0 + row)) * INNERq + h*DHq + c4];
        Qt[(c4+0)*ATT_STRIDE + row] = qv.x;
        Qt[(c4+1)*ATT_STRIDE + row] = qv.y;
        Qt[(c4+2)*ATT_STRIDE + row] = qv.z;
        Qt[(c4+3)*ATT_STRIDE + row] = qv.w;
    }
    if (t < 64) {
        lci_row[t]  = g_lc[(size_t)bh*Sq + i0 + t];
        m_row[t]    = -3.4e38f;
        ssum_row[t] = 0.f;
    }

    float acc[4][4];
    #pragma unroll
    for (int a = 0; a < 4; a++)
        #pragma unroll
        for (int d = 0; d < 4; d++) acc[a][d] = 0.f;

    for (int jt = 0; jt <= it; jt++) {
        int j0 = jt * 64;
        __syncthreads();   // S1: prev tile consumed (and init visible on first iter)

        // load K^T (scaled)
        #pragma unroll
        for (int e4 = 0; e4 < 4; e4++) {
            int e = t + 256*e4;
            int row = e >> 4, c4 = (e & 15) << 2;
            float4 kv = *(const float4*)&g_k[((size_t)(b*Sq + j0 + row)) * INNERq + h*DHq + c4];
            KV[(c4+0)*ATT_STRIDE + row] = kv.x*0.125f;
            KV[(c4+1)*ATT_STRIDE + row] = kv.y*0.125f;
            KV[(c4+2)*ATT_STRIDE + row] = kv.z*0.125f;
            KV[(c4+3)*ATT_STRIDE + row] = kv.w*0.125f;
        }
        // warp 0: prefix-max + ej over 64 cols, then per-row state for 64 rows
        if (t < 32) {
            int l = t;
            size_t gbase = (size_t)bh*Sq + j0;
            float a0 = g_ig[gbase + l]      - g_lc[gbase + l];
            float a1 = g_ig[gbase + 32 + l] - g_lc[gbase + 32 + l];
            float p0 = a0;
            #pragma unroll
            for (int off = 1; off < 32; off <<= 1) {
                float u = __shfl_up_sync(0xffffffffu, p0, off);
                if (l >= off) p0 = fmaxf(p0, u);
            }
            float max0 = __shfl_sync(0xffffffffu, p0, 31);
            float p1 = a1;
            #pragma unroll
            for (int off = 1; off < 32; off <<= 1) {
                float u = __shfl_up_sync(0xffffffffu, p1, off);
                if (l >= off) p1 = fmaxf(p1, u);
            }
            p1 = fmaxf(p1, max0);
            float pmAll = __shfl_sync(0xffffffffu, p1, 31);
            pm[l]      = p0;
            pm[32 + l] = p1;
            ej[l]      = __expf(a0 - pmAll);
            ej[32 + l] = __expf(a1 - pmAll);
            __syncwarp();
            #pragma unroll
            for (int half = 0; half < 2; half++) {
                int r = l + 32*half;
                int jm = i0 + r - j0 + 1;          // >=1 since j0 <= i0
                jm = jm > 64 ? 64 : jm;
                float mo = m_row[r];
                float rowmax = lci_row[r] + pm[jm-1];
                float mnew = fmaxf(mo, rowmax);
                float sc = __expf(mo - mnew);      // 0 first tile, 1 if unchanged
                sc_row[r] = sc;
                Ei_row[r] = __expf(lci_row[r] + pmAll - mnew);
                m_row[r]  = mnew;
                ssum_row[r] *= sc;
            }
        }
        __syncthreads();   // S2

        // rescale O accumulators
        #pragma unroll
        for (int a = 0; a < 4; a++) {
            float sc = sc_row[4*ty + a];
            #pragma unroll
            for (int d = 0; d < 4; d++) acc[a][d] *= sc;
        }

        // phase 1: S(4x4) = Q @ K^T over 64 dims
        float s[4][4];
        #pragma unroll
        for (int a = 0; a < 4; a++)
            #pragma unroll
            for (int c = 0; c < 4; c++) s[a][c] = 0.f;
        #pragma unroll 8
        for (int kk = 0; kk < 64; kk++) {
            float4 aq = *(const float4*)&Qt[kk*ATT_STRIDE + 4*ty];
            float4 bk = *(const float4*)&KV[kk*ATT_STRIDE + 4*tx];
            s[0][0] += aq.x*bk.x; s[0][1] += aq.x*bk.y; s[0][2] += aq.x*bk.z; s[0][3] += aq.x*bk.w;
            s[1][0] += aq.y*bk.x; s[1][1] += aq.y*bk.y; s[1][2] += aq.y*bk.z; s[1][3] += aq.y*bk.w;
            s[2][0] += aq.z*bk.x; s[2][1] += aq.z*bk.y; s[2][2] += aq.z*bk.z; s[2][3] += aq.z*bk.w;
            s[3][0] += aq.w*bk.x; s[3][1] += aq.w*bk.y; s[3][2] += aq.w*bk.z; s[3][3] += aq.w*bk.w;
        }
        // weights (+ causal mask on diag), P store (row-major), row-sum butterfly
        {
            float e0 = ej[4*tx], e1 = ej[4*tx+1], e2 = ej[4*tx+2], e3 = ej[4*tx+3];
            bool diag = (jt == it);
            int jg = j0 + 4*tx;
            #pragma unroll
            for (int a = 0; a < 4; a++) {
                int rr = 4*ty + a;
                float Ei = Ei_row[rr];
                float p0 = s[a][0]*Ei*e0;
                float p1 = s[a][1]*Ei*e1;
                float p2 = s[a][2]*Ei*e2;
                float p3 = s[a][3]*Ei*e3;
                if (diag) {
                    int ig = i0 + rr;
                    if (jg     > ig) p0 = 0.f;
                    if (jg + 1 > ig) p1 = 0.f;
                    if (jg + 2 > ig) p2 = 0.f;
                    if (jg + 3 > ig) p3 = 0.f;
                }
                *(float4*)&Pt[rr*ATT_STRIDE + 4*tx] = make_float4(p0, p1, p2, p3);
                float part = (p0 + p1) + (p2 + p3);
                part += __shfl_xor_sync(0xffffffffu, part, 1);
                part += __shfl_xor_sync(0xffffffffu, part, 2);
                part += __shfl_xor_sync(0xffffffffu, part, 4);
                part += __shfl_xor_sync(0xffffffffu, part, 8);
                if (tx == 0) ssum_row[rr] += part;
            }
        }
        __syncthreads();   // S3: phase 1 done with K

        // load V (row-major) into KV
        #pragma unroll
        for (int e4 = 0; e4 < 4; e4++) {
            int e = t + 256*e4;
            int row = e >> 4, c4 = (e & 15) << 2;
            *(float4*)&KV[row*ATT_STRIDE + c4] =
                *(const float4*)&g_v[((size_t)(b*Sq + j0 + row)) * INNERq + h*DHq + c4];
        }
        __syncthreads();   // S4: V + P ready

        // phase 2: O(4x4) += P @ V, j unrolled by 4
        #pragma unroll 4
        for (int jj = 0; jj < 64; jj += 4) {
            float4 pa0 = *(const float4*)&Pt[(4*ty+0)*ATT_STRIDE + jj];
            float4 pa1 = *(const float4*)&Pt[(4*ty+1)*ATT_STRIDE + jj];
            float4 pa2 = *(const float4*)&Pt[(4*ty+2)*ATT_STRIDE + jj];
            float4 pa3 = *(const float4*)&Pt[(4*ty+3)*ATT_STRIDE + jj];
            float4 vb0 = *(const float4*)&KV[(jj+0)*ATT_STRIDE + 4*tx];
            float4 vb1 = *(const float4*)&KV[(jj+1)*ATT_STRIDE + 4*tx];
            float4 vb2 = *(const float4*)&KV[(jj+2)*ATT_STRIDE + 4*tx];
            float4 vb3 = *(const float4*)&KV[(jj+3)*ATT_STRIDE + 4*tx];
            acc[0][0] += pa0.x*vb0.x + pa0.y*vb1.x + pa0.z*vb2.x + pa0.w*vb3.x;
            acc[0][1] += pa0.x*vb0.y + pa0.y*vb1.y + pa0.z*vb2.y + pa0.w*vb3.y;
            acc[0][2] += pa0.x*vb0.z + pa0.y*vb1.z + pa0.z*vb2.z + pa0.w*vb3.z;
            acc[0][3] += pa0.x*vb0.w + pa0.y*vb1.w + pa0.z*vb2.w + pa0.w*vb3.w;
            acc[1][0] += pa1.x*vb0.x + pa1.y*vb1.x + pa1.z*vb2.x + pa1.w*vb3.x;
            acc[1][1] += pa1.x*vb0.y + pa1.y*vb1.y + pa1.z*vb2.y + pa1.w*vb3.y;
            acc[1][2] += pa1.x*vb0.z + pa1.y*vb1.z + pa1.z*vb2.z + pa1.w*vb3.z;
            acc[1][3] += pa1.x*vb0.w + pa1.y*vb1.w + pa1.z*vb2.w + pa1.w*vb3.w;
            acc[2][0] += pa2.x*vb0.x + pa2.y*vb1.x + pa2.z*vb2.x + pa2.w*vb3.x;
            acc[2][1] += pa2.x*vb0.y + pa2.y*vb1.y + pa2.z*vb2.y + pa2.w*vb3.y;
            acc[2][2] += pa2.x*vb0.z + pa2.y*vb1.z + pa2.z*vb2.z + pa2.w*vb3.z;
            acc[2][3] += pa2.x*vb0.w + pa2.y*vb1.w + pa2.z*vb2.w + pa2.w*vb3.w;
            acc[3][0] += pa3.x*vb0.x + pa3.y*vb1.x + pa3.z*vb2.x + pa3.w*vb3.x;
            acc[3][1] += pa3.x*vb0.y + pa3.y*vb1.y + pa3.z*vb2.y + pa3.w*vb3.y;
            acc[3][2] += pa3.x*vb0.z + pa3.y*vb1.z + pa3.z*vb2.z + pa3.w*vb3.z;
            acc[3][3] += pa3.x*vb0.w + pa3.y*vb1.w + pa3.z*vb2.w + pa3.w*vb3.w;
        }
    }

    // stage O row-major into Qt
    #pragma unroll
    for (int a = 0; a < 4; a++)
        *(float4*)&Qt[(4*ty + a)*ATT_STRIDE + 4*tx] =
            make_float4(acc[a][0], acc[a][1], acc[a][2], acc[a][3]);
    __syncthreads();

    // LN + skip + silu(z): thread = (row = t>>2, quarter qd = t&3)
    {
        int row = t >> 2, qd = t & 3;
        int i = i0 + row;
        float m    = m_row[row];
        float ssum = ssum_row[row];
        float denom = fmaxf(fabsf(ssum), __expf(-m)) + 1e-6f;
        float inv = 1.f / denom;
        float o[16];
        #pragma unroll
        for (int k4 = 0; k4 < 4; k4++) {
            float4 v = *(const float4*)&Qt[row*ATT_STRIDE + qd*16 + k4*4];
            o[k4*4+0] = v.x*inv; o[k4*4+1] = v.y*inv; o[k4*4+2] = v.z*inv; o[k4*4+3] = v.w*inv;
        }
        float mean = 0.f;
        #pragma unroll
        for (int d = 0; d < 16; d++) mean += o[d];
        mean += __shfl_xor_sync(0xffffffffu, mean, 1);
        mean += __shfl_xor_sync(0xffffffffu, mean, 2);
        mean *= (1.f / 64.f);
        float var = 0.f;
        #pragma unroll
        for (int d = 0; d < 16; d++) { float df = o[d] - mean; var += df * df; }
        var += __shfl_xor_sync(0xffffffffu, var, 1);
        var += __shfl_xor_sync(0xffffffffu, var, 2);
        var *= (1.f / 64.f);
        float rstd = rsqrtf(var + 1e-5f);
        size_t obase = ((size_t)(b*Sq + i)) * INNERq + h*DHq + qd*16;
        #pragma unroll
        for (int d = 0; d < 16; d++) {
            int c = h*DHq + qd*16 + d;
            float hn  = (o[d] - mean) * rstd * norm_w[c];
            float za  = g_z[obase + d];
            float sil = za / (1.f + __expf(-za));
            g_h[obase + d] = (hn + skipw[c] * g_xa[obase + d]) * sil;
        }
    }
}

// ---------------- launch (graph-capturable; attribute set is not a stream op) ----------------
extern "C" void kernel_launch(void* const* d_in, const int* in_sizes, int n_in,
                              void* d_out, int out_size)
{
    const float* x      = (const float*)d_in[0];
    const float* W_up   = (const float*)d_in[1];
    const float* conv_w = (const float*)d_in[2];
    const float* conv_b = (const float*)d_in[3];
    const float* Wq     = (const float*)d_in[4];
    const float* Wk     = (const float*)d_in[5];
    const float* Wv     = (const float*)d_in[6];
    const float* W_i    = (const float*)d_in[7];
    const float* b_i    = (const float*)d_in[8];
    const float* W_f    = (const float*)d_in[9];
    const float* b_f    = (const float*)d_in[10];
    const float* norm_w = (const float*)d_in[11];
    const float* skipw  = (const float*)d_in[12];
    const float* W_down = (const float*)d_in[13];
    float* out = (float*)d_out;

    cudaFuncSetAttribute(attn_kernel,
                         cudaFuncAttributeMaxDynamicSharedMemorySize, ATT_SMEM_BYTES);

    gemm_nt<0><<<dim3(16, 64), 256>>>(x, W_up, nullptr, Cdim);
    fused_conv_qkv_gates<<<Bq*Sq, 128>>>(conv_w, conv_b, Wq, Wk, Wv, W_i, b_i, W_f, b_f);
    scan_kernel<<<Bq*NHq, 1024>>>();
    attn_kernel<<<512, 256, ATT_SMEM_BYTES>>>(norm_w, skipw);
    gemm_nt<1><<<dim3(4, 64), 256>>>(nullptr, W_down, out, INNERq);
}